// round 1
// baseline (speedup 1.0000x reference)
#include <cuda_runtime.h>
#include <math.h>

#define DD   128   // embedding dim
#define CC   64    // categories
#define LL   64    // leaves
#define KC   32    // k chunk
#define PAD  132   // smem row stride (multiple of 4 for float4, avoids worst conflicts)
#define BT   128   // b-rows per block
#define LT   128   // l-cols per block (2 categories)

// Scratch (allocation-free: __device__ globals)
__device__ float g_inv_xnorm[65536];
__device__ float g_inv_enorm[4096];

__device__ __forceinline__ void ffma2(unsigned long long &d,
                                      unsigned long long a,
                                      unsigned long long b) {
    asm("fma.rn.f32x2 %0, %1, %2, %0;" : "+l"(d) : "l"(a), "l"(b));
}
__device__ __forceinline__ unsigned long long dup2(float a) {
    unsigned long long r;
    unsigned int ai = __float_as_uint(a);
    asm("mov.b64 %0, {%1, %1};" : "=l"(r) : "r"(ai));
    return r;
}

__global__ void xnorm_kernel(const float* __restrict__ x, int B) {
    int row  = blockIdx.x * 8 + (threadIdx.x >> 5);
    if (row >= B) return;
    int lane = threadIdx.x & 31;
    float4 v = *reinterpret_cast<const float4*>(x + (size_t)row * DD + lane * 4);
    float s = v.x * v.x + v.y * v.y + v.z * v.z + v.w * v.w;
#pragma unroll
    for (int o = 16; o > 0; o >>= 1) s += __shfl_xor_sync(0xffffffffu, s, o);
    if (lane == 0) g_inv_xnorm[row] = 1.0f / fmaxf(sqrtf(s), 1e-8f);
}

__global__ void enorm_kernel(const float* __restrict__ e) {
    int row  = blockIdx.x * 8 + (threadIdx.x >> 5);
    if (row >= CC * LL) return;
    int lane = threadIdx.x & 31;
    float4 v = *reinterpret_cast<const float4*>(e + (size_t)row * DD + lane * 4);
    float s = v.x * v.x + v.y * v.y + v.z * v.z + v.w * v.w;
#pragma unroll
    for (int o = 16; o > 0; o >>= 1) s += __shfl_xor_sync(0xffffffffu, s, o);
    if (lane == 0) g_inv_enorm[row] = 1.0f / fmaxf(sqrtf(s), 1e-8f);
}

__global__ void init_counts_kernel(const float* __restrict__ leaf,
                                   float* __restrict__ counts) {
    int i = blockIdx.x * blockDim.x + threadIdx.x;
    if (i < CC * LL) counts[i] = leaf[i];
}

__global__ __launch_bounds__(256)
void cosmax_kernel(const float* __restrict__ x, const float* __restrict__ e,
                   float* __restrict__ cos_out, float* __restrict__ counts, int B)
{
    __shared__ __align__(16) float pool[2 * KC * PAD];   // tiles, later reused for reduction
    __shared__ float hist[2 * LL];

    const int tid = threadIdx.x;
    const int tx  = tid & 15;     // b-microtile index (8 rows each)
    const int ty  = tid >> 4;     // l-microtile index (8 cols each)
    const int b0  = blockIdx.x * BT;
    const int l0  = blockIdx.y * LT;   // flattened C*L row offset

    float* xs = pool;              // [KC][PAD], transposed: xs[k][b]
    float* es = pool + KC * PAD;   // [KC][PAD], transposed: es[k][l]

    unsigned long long acc[8][4];  // 8 b-rows x 4 packed-l-pairs (=> 8x8 fp32)
#pragma unroll
    for (int i = 0; i < 8; i++)
#pragma unroll
        for (int j = 0; j < 4; j++) acc[i][j] = 0ull;

    const int lrow = tid >> 3;     // 0..31
    const int c4   = tid & 7;      // 0..7 (float4 column)

    for (int kc = 0; kc < DD; kc += KC) {
        __syncthreads();
#pragma unroll
        for (int it = 0; it < 4; it++) {
            int r = it * 32 + lrow;
            float4 vx = *reinterpret_cast<const float4*>(
                x + (size_t)(b0 + r) * DD + kc + c4 * 4);
            float4 ve = *reinterpret_cast<const float4*>(
                e + (size_t)(l0 + r) * DD + kc + c4 * 4);
            xs[(c4 * 4 + 0) * PAD + r] = vx.x;
            xs[(c4 * 4 + 1) * PAD + r] = vx.y;
            xs[(c4 * 4 + 2) * PAD + r] = vx.z;
            xs[(c4 * 4 + 3) * PAD + r] = vx.w;
            es[(c4 * 4 + 0) * PAD + r] = ve.x;
            es[(c4 * 4 + 1) * PAD + r] = ve.y;
            es[(c4 * 4 + 2) * PAD + r] = ve.z;
            es[(c4 * 4 + 3) * PAD + r] = ve.w;
        }
        __syncthreads();
#pragma unroll 4
        for (int k = 0; k < KC; k++) {
            float4 a0 = *reinterpret_cast<const float4*>(&xs[k * PAD + tx * 8]);
            float4 a1 = *reinterpret_cast<const float4*>(&xs[k * PAD + tx * 8 + 4]);
            ulonglong2 bv0 = *reinterpret_cast<const ulonglong2*>(&es[k * PAD + ty * 8]);
            ulonglong2 bv1 = *reinterpret_cast<const ulonglong2*>(&es[k * PAD + ty * 8 + 4]);
            unsigned long long bb[4] = {bv0.x, bv0.y, bv1.x, bv1.y};
            float av[8] = {a0.x, a0.y, a0.z, a0.w, a1.x, a1.y, a1.z, a1.w};
#pragma unroll
            for (int i = 0; i < 8; i++) {
                unsigned long long a2 = dup2(av[i]);
#pragma unroll
                for (int j = 0; j < 4; j++) ffma2(acc[i][j], a2, bb[j]);
            }
        }
    }
    __syncthreads();

    // --- epilogue: per-(b,category) max+argmax with e-norm applied ---
    float* rmax = pool;                                   // [16][128]
    int*   rarg = reinterpret_cast<int*>(pool + 16 * 128); // [16][128]
    {
        float en[8];
#pragma unroll
        for (int j = 0; j < 8; j++) en[j] = g_inv_enorm[l0 + ty * 8 + j];
#pragma unroll
        for (int i = 0; i < 8; i++) {
            float m = __int_as_float(0xff800000); // -inf
            int arg = 0;
#pragma unroll
            for (int j = 0; j < 4; j++) {
                unsigned long long u = acc[i][j];
                float v0 = __uint_as_float((unsigned int)u)          * en[2 * j];
                float v1 = __uint_as_float((unsigned int)(u >> 32))  * en[2 * j + 1];
                if (v0 > m) { m = v0; arg = ty * 8 + 2 * j; }
                if (v1 > m) { m = v1; arg = ty * 8 + 2 * j + 1; }
            }
            rmax[ty * 128 + tx * 8 + i] = m;
            rarg[ty * 128 + tx * 8 + i] = arg;
        }
    }
    if (tid < 2 * LL) hist[tid] = 0.0f;
    __syncthreads();
    {
        int b   = tid & 127;
        int cat = tid >> 7;    // 0 or 1 within this block
        float m = __int_as_float(0xff800000);
        int arg = 0;
#pragma unroll
        for (int t = 0; t < 8; t++) {
            float v = rmax[(cat * 8 + t) * 128 + b];
            if (v > m) { m = v; arg = rarg[(cat * 8 + t) * 128 + b]; }
        }
        int gb = b0 + b;
        cos_out[(size_t)gb * CC + (l0 >> 6) + cat] = m * g_inv_xnorm[gb];
        atomicAdd(&hist[cat * LL + (arg & 63)], 1.0f);
    }
    __syncthreads();
    if (tid < 2 * LL) {
        float v = hist[tid];
        if (v != 0.0f)
            atomicAdd(&counts[((l0 >> 6) + (tid >> 6)) * LL + (tid & 63)], v);
    }
}

extern "C" void kernel_launch(void* const* d_in, const int* in_sizes, int n_in,
                              void* d_out, int out_size) {
    const float* x    = (const float*)d_in[0];
    const float* e    = (const float*)d_in[1];
    const float* leaf = (const float*)d_in[2];
    const int B = in_sizes[0] / DD;           // 65536

    float* cos_out = (float*)d_out;           // [B, C]
    float* counts  = cos_out + (size_t)B * CC; // [C, L]

    xnorm_kernel<<<B / 8, 256>>>(x, B);
    enorm_kernel<<<(CC * LL) / 8, 256>>>(e);
    init_counts_kernel<<<(CC * LL + 255) / 256, 256>>>(leaf, counts);

    dim3 grid(B / BT, (CC * LL) / LT);        // (512, 32)
    cosmax_kernel<<<grid, 256>>>(x, e, cos_out, counts, B);
}

// round 3
// speedup vs baseline: 3.7940x; 3.7940x over previous
#include <cuda_runtime.h>
#include <cuda_bf16.h>
#include <math.h>

#define DD   128
#define CC   64
#define LL   64
#define KSPLIT 384            // [hi | lo | hi] packed K
#define BT   128              // b rows per CTA
#define NTT  128              // l cols per CTA (2 categories)
#define KC   64               // k per chunk
#define NCHUNK 6
#define NSTAGE 3
#define STAGE_BYTES 32768     // 16KB A + 16KB B per stage

// ---- device scratch (allocation-free) ----
__device__ __nv_bfloat16 gA[65536ull * KSPLIT];   // ~50 MB
__device__ __nv_bfloat16 gB[4096ull  * KSPLIT];

__device__ __forceinline__ unsigned smem_u32(const void* p) {
    unsigned a;
    asm("{ .reg .u64 t; cvta.to.shared.u64 t, %1; cvt.u32.u64 %0, t; }" : "=r"(a) : "l"(p));
    return a;
}
template<int N> __device__ __forceinline__ void cp_wait() {
    asm volatile("cp.async.wait_group %0;" :: "n"(N) : "memory");
}

// ---------------- prep: normalize + bf16 split-pack ----------------
template<int ROWS_TOTAL>
__global__ void split_pack_kernel(const float* __restrict__ src, __nv_bfloat16* __restrict__ dst) {
    int row  = blockIdx.x * 8 + (threadIdx.x >> 5);
    if (row >= ROWS_TOTAL) return;
    int lane = threadIdx.x & 31;
    float4 v = *reinterpret_cast<const float4*>(src + (size_t)row * DD + lane * 4);
    float s = v.x * v.x + v.y * v.y + v.z * v.z + v.w * v.w;
#pragma unroll
    for (int o = 16; o > 0; o >>= 1) s += __shfl_xor_sync(0xffffffffu, s, o);
    float inv = 1.0f / fmaxf(sqrtf(s), 1e-8f);

    float f[4] = {v.x * inv, v.y * inv, v.z * inv, v.w * inv};
    unsigned short hi[4], lo[4];
#pragma unroll
    for (int i = 0; i < 4; i++) {
        __nv_bfloat16 h = __float2bfloat16_rn(f[i]);
        __nv_bfloat16 l = __float2bfloat16_rn(f[i] - __bfloat162float(h));
        hi[i] = __bfloat16_as_ushort(h);
        lo[i] = __bfloat16_as_ushort(l);
    }
    uint2 hp = make_uint2((unsigned)hi[0] | ((unsigned)hi[1] << 16),
                          (unsigned)hi[2] | ((unsigned)hi[3] << 16));
    uint2 lp = make_uint2((unsigned)lo[0] | ((unsigned)lo[1] << 16),
                          (unsigned)lo[2] | ((unsigned)lo[3] << 16));
    size_t base = (size_t)row * KSPLIT + lane * 4;
    if (ROWS_TOTAL == 65536) {          // A pack: [hi | lo | hi]
        *reinterpret_cast<uint2*>(dst + base)       = hp;
        *reinterpret_cast<uint2*>(dst + base + 128) = lp;
        *reinterpret_cast<uint2*>(dst + base + 256) = hp;
    } else {                            // B pack: [hi | hi | lo]
        *reinterpret_cast<uint2*>(dst + base)       = hp;
        *reinterpret_cast<uint2*>(dst + base + 128) = hp;
        *reinterpret_cast<uint2*>(dst + base + 256) = lp;
    }
}

__global__ void init_counts_kernel(const float* __restrict__ leaf, float* __restrict__ counts) {
    int i = blockIdx.x * blockDim.x + threadIdx.x;
    if (i < CC * LL) counts[i] = leaf[i];
}

// ---------------- main fused GEMM + max/argmax (mma.sync) ----------------
__global__ __launch_bounds__(256, 2)
void cosmax_mma_kernel(float* __restrict__ cos_out, float* __restrict__ counts) {
    extern __shared__ char smem[];
    __shared__ float hist[128];
    const unsigned sb = smem_u32(smem);
    const int tid  = threadIdx.x;
    const int lane = tid & 31;
    const int wid  = tid >> 5;
    const int wm   = wid >> 1;     // 0..3 : warp row (32 b-rows)
    const int wn   = wid & 1;      // 0..1 : category within CTA
    const int b0   = blockIdx.x * BT;
    const int l0   = blockIdx.y * NTT;
    if (tid < 128) hist[tid] = 0.0f;

    float acc[2][8][4];
#pragma unroll
    for (int mt = 0; mt < 2; mt++)
#pragma unroll
        for (int nt = 0; nt < 8; nt++)
#pragma unroll
            for (int c = 0; c < 4; c++) acc[mt][nt][c] = 0.0f;

    // cp.async loader mapping: 2 threads per 128B row
    const int lr  = tid >> 1;
    const int lj0 = (tid & 1) * 4;
    const unsigned lxor = (unsigned)(lr & 7) << 4;

#define ISSUE(c)                                                                     \
    {                                                                                \
        unsigned s_ = sb + ((c) % NSTAGE) * STAGE_BYTES;                             \
        const char* ga_ = (const char*)(gA + (size_t)(b0 + lr) * KSPLIT + (c) * KC); \
        const char* gb_ = (const char*)(gB + (size_t)(l0 + lr) * KSPLIT + (c) * KC); \
        _Pragma("unroll")                                                            \
        for (int j = 0; j < 4; j++) {                                                \
            unsigned off_ = (unsigned)lr * 128u + (unsigned)(lj0 + j) * 16u;         \
            unsigned sw_  = off_ ^ lxor;                                             \
            asm volatile("cp.async.cg.shared.global [%0],[%1],16;"                   \
                         :: "r"(s_ + sw_), "l"(ga_ + (lj0 + j) * 16) : "memory");    \
            asm volatile("cp.async.cg.shared.global [%0],[%1],16;"                   \
                         :: "r"(s_ + 16384u + sw_), "l"(gb_ + (lj0 + j) * 16) : "memory"); \
        }                                                                            \
        asm volatile("cp.async.commit_group;" ::: "memory");                         \
    }

    ISSUE(0); ISSUE(1); ISSUE(2);

#pragma unroll
    for (int c = 0; c < NCHUNK; c++) {
        if (c < NCHUNK - 2)       cp_wait<2>();
        else if (c == NCHUNK - 2) cp_wait<1>();
        else                      cp_wait<0>();
        __syncthreads();

        const unsigned s = sb + (c % NSTAGE) * STAGE_BYTES;
#pragma unroll
        for (int ks = 0; ks < 4; ks++) {
            unsigned af[2][4];
#pragma unroll
            for (int mt = 0; mt < 2; mt++) {
                int row = wm * 32 + mt * 16 + (lane & 15);
                unsigned off = (unsigned)row * 128u + (unsigned)ks * 32u + ((lane >> 4) * 16u);
                unsigned addr = s + (off ^ ((unsigned)(row & 7) << 4));
                asm volatile("ldmatrix.sync.aligned.m8n8.x4.shared.b16 {%0,%1,%2,%3},[%4];"
                             : "=r"(af[mt][0]), "=r"(af[mt][1]), "=r"(af[mt][2]), "=r"(af[mt][3])
                             : "r"(addr));
            }
            unsigned bf[8][2];
#pragma unroll
            for (int np = 0; np < 4; np++) {
                int row = wn * 64 + np * 16 + ((lane & 16) >> 1) + (lane & 7);
                unsigned off = (unsigned)row * 128u + (unsigned)ks * 32u + ((lane & 8) ? 16u : 0u);
                unsigned addr = s + 16384u + (off ^ ((unsigned)(row & 7) << 4));
                asm volatile("ldmatrix.sync.aligned.m8n8.x4.shared.b16 {%0,%1,%2,%3},[%4];"
                             : "=r"(bf[2*np][0]), "=r"(bf[2*np][1]),
                               "=r"(bf[2*np+1][0]), "=r"(bf[2*np+1][1])
                             : "r"(addr));
            }
#pragma unroll
            for (int mt = 0; mt < 2; mt++)
#pragma unroll
                for (int nt = 0; nt < 8; nt++)
                    asm volatile(
                        "mma.sync.aligned.m16n8k16.row.col.f32.bf16.bf16.f32 "
                        "{%0,%1,%2,%3},{%4,%5,%6,%7},{%8,%9},{%0,%1,%2,%3};"
                        : "+f"(acc[mt][nt][0]), "+f"(acc[mt][nt][1]),
                          "+f"(acc[mt][nt][2]), "+f"(acc[mt][nt][3])
                        : "r"(af[mt][0]), "r"(af[mt][1]), "r"(af[mt][2]), "r"(af[mt][3]),
                          "r"(bf[nt][0]), "r"(bf[nt][1]));
        }
        __syncthreads();
        if (c + NSTAGE < NCHUNK) {
            const int cn = c + NSTAGE;
            ISSUE(cn);
        }
    }

    // ---- epilogue: in-register max/argmax, quad shuffle reduce ----
    const int qcol = (lane & 3) * 2;       // this thread's col pair base within n-tile
#pragma unroll
    for (int mt = 0; mt < 2; mt++) {
#pragma unroll
        for (int h = 0; h < 2; h++) {      // acc half: rows lane/4 (+0) vs +8
            float m = __int_as_float(0xff800000);
            int arg = 0;
#pragma unroll
            for (int nt = 0; nt < 8; nt++) {
                float v0 = acc[mt][nt][2 * h];
                float v1 = acc[mt][nt][2 * h + 1];
                int c0 = nt * 8 + qcol;
                if (v0 > m) { m = v0; arg = c0; }
                if (v1 > m) { m = v1; arg = c0 + 1; }
            }
#pragma unroll
            for (int off = 1; off <= 2; off <<= 1) {
                float om = __shfl_xor_sync(0xffffffffu, m, off);
                int   oa = __shfl_xor_sync(0xffffffffu, arg, off);
                if (om > m || (om == m && oa < arg)) { m = om; arg = oa; }
            }
            if ((lane & 3) == 0) {
                int row = b0 + wm * 32 + mt * 16 + h * 8 + (lane >> 2);
                cos_out[(size_t)row * CC + blockIdx.y * 2 + wn] = m;
                atomicAdd(&hist[wn * LL + arg], 1.0f);
            }
        }
    }
    __syncthreads();
    if (tid < 128) {
        float v = hist[tid];
        if (v != 0.0f)
            atomicAdd(&counts[(blockIdx.y * 2 + (tid >> 6)) * LL + (tid & 63)], v);
    }
#undef ISSUE
}

extern "C" void kernel_launch(void* const* d_in, const int* in_sizes, int n_in,
                              void* d_out, int out_size) {
    const float* x    = (const float*)d_in[0];
    const float* e    = (const float*)d_in[1];
    const float* leaf = (const float*)d_in[2];
    const int B = in_sizes[0] / DD;            // 65536

    float* cos_out = (float*)d_out;            // [B, C]
    float* counts  = cos_out + (size_t)B * CC; // [C, L]

    __nv_bfloat16 *pA, *pB;
    cudaGetSymbolAddress((void**)&pA, gA);
    cudaGetSymbolAddress((void**)&pB, gB);

    cudaFuncSetAttribute(cosmax_mma_kernel,
                         cudaFuncAttributeMaxDynamicSharedMemorySize, NSTAGE * STAGE_BYTES);

    split_pack_kernel<65536><<<B / 8, 256>>>(x, pA);
    split_pack_kernel<4096><<<(CC * LL) / 8, 256>>>(e, pB);
    init_counts_kernel<<<(CC * LL + 255) / 256, 256>>>(leaf, counts);

    dim3 grid(B / BT, (CC * LL) / NTT);        // (512, 32)
    cosmax_mma_kernel<<<grid, 256, NSTAGE * STAGE_BYTES>>>(cos_out, counts);
}